// round 6
// baseline (speedup 1.0000x reference)
#include <cuda_runtime.h>
#include <math.h>

#define BB 32
#define SS 1024
#define NTOK (BB*SS)      // 32768 tokens
#define HH 32
#define WW 32
#define HWB (HH*WW)       // 1024 bins
#define P2 256
#define CC 3
#define DD (CC*P2)        // 768
#define MAXB 192          // max tokens per bin we store (E[cnt]=28.8, sigma~5.4)
#define EPSV 1e-6f

// ---- scratch (device globals; no allocation) ----
__device__ int   g_bincount[HWB];
__device__ int   g_binlist[HWB * MAXB];   // 768 KB
__device__ float g_mnew[HWB * P2];        // mean_new       (1 MB)
__device__ float g_rstd[HWB * P2];        // 1/(std+eps)    (1 MB)

// ---------------------------------------------------------------------------
// K0: zero bin counters (graph replays -> must reset every launch)
// ---------------------------------------------------------------------------
__global__ void k_zero() {
    int i = blockIdx.x * blockDim.x + threadIdx.x;
    if (i < HWB) g_bincount[i] = 0;
}

// ---------------------------------------------------------------------------
// K1: bin valid tokens by flat grid index pf
//     mask read as int32 (jax bool widened by harness); nonzero = padding
// ---------------------------------------------------------------------------
__global__ void k_bin(const int* __restrict__ pos_h,
                      const int* __restrict__ pos_w,
                      const int* __restrict__ mask) {
    int t = blockIdx.x * blockDim.x + threadIdx.x;
    if (t >= NTOK) return;
    if (mask[t] != 0) return;
    int pf = pos_h[t] * WW + pos_w[t];
    int idx = atomicAdd(&g_bincount[pf], 1);
    if (idx < MAXB) g_binlist[pf * MAXB + idx] = t;
}

// ---------------------------------------------------------------------------
// K2: per-bin Welford update + rstd, one block per bin, thread = p column.
//     a_i = xbar_i - mean_old ;  S1 = sum a_i ;  S2 = sum a_i^2
//     mean_new = mo + S1/n_g ;  m2_new = m2 + S2 - (S1/n_g)*S1
// ---------------------------------------------------------------------------
__global__ void __launch_bounds__(P2) k_stats(const float* __restrict__ patches,
                                              const float* __restrict__ n_in,
                                              const float* __restrict__ mean_in,
                                              const float* __restrict__ m2_in) {
    int bin = blockIdx.x;
    int p = threadIdx.x;                         // 0..255

    __shared__ int s_tok[MAXB];
    __shared__ int s_cnt;
    if (p == 0) s_cnt = min(g_bincount[bin], MAXB);
    __syncthreads();
    int cnt = s_cnt;
    for (int i = p; i < cnt; i += P2) s_tok[i] = g_binlist[bin * MAXB + i];
    __syncthreads();

    float mo = mean_in[(size_t)bin * P2 + p];
    float s1 = 0.f, s2 = 0.f;
    const float c3 = 1.0f / 3.0f;

    int i = 0;
    for (; i + 2 <= cnt; i += 2) {               // unroll 2 for MLP
        const float* b0 = patches + (size_t)s_tok[i]     * DD;
        const float* b1 = patches + (size_t)s_tok[i + 1] * DD;
        float x00 = b0[p], x01 = b0[p + 256], x02 = b0[p + 512];
        float x10 = b1[p], x11 = b1[p + 256], x12 = b1[p + 512];
        float a0 = (x00 + x01 + x02) * c3 - mo;
        float a1 = (x10 + x11 + x12) * c3 - mo;
        s1 += a0; s2 += a0 * a0;
        s1 += a1; s2 += a1 * a1;
    }
    if (i < cnt) {
        const float* b0 = patches + (size_t)s_tok[i] * DD;
        float a0 = (b0[p] + b0[p + 256] + b0[p + 512]) * c3 - mo;
        s1 += a0; s2 += a0 * a0;
    }

    float nn  = n_in[bin] + (float)cnt;          // n_new for this bin
    float ng  = fmaxf(nn, 1.0f);
    float u   = s1 / ng;                          // mean shift
    float mnv = mo + u;                           // mean_new
    float m2v = m2_in[(size_t)bin * P2 + p] + (s2 - u * s1);
    float var = (nn < 2.0f) ? 1.0f : (m2v / ng);

    g_mnew[(size_t)bin * P2 + p] = mnv;
    g_rstd[(size_t)bin * P2 + p] = 1.0f / (sqrtf(var) + EPSV);
}

// ---------------------------------------------------------------------------
// K3: normalize: out = (x - mean_new[pf,p]) * rstd[pf,p], 0 on padding.
//     one thread per float4 of the (NTOK,768) tensor
// ---------------------------------------------------------------------------
__global__ void k_norm(const float* __restrict__ patches,
                       const int* __restrict__ pos_h,
                       const int* __restrict__ pos_w,
                       const int* __restrict__ mask,
                       float* __restrict__ out) {
    int i = blockIdx.x * blockDim.x + threadIdx.x;   // float4 index
    if (i >= NTOK * DD / 4) return;
    int t = i / (DD / 4);                            // DD/4 = 192
    int r = i - t * (DD / 4);
    int d = r * 4;
    int p = d & (P2 - 1);                            // stat index (channel-invariant)

    if (mask[t] != 0) {
        ((float4*)out)[i] = make_float4(0.f, 0.f, 0.f, 0.f);
        return;
    }
    int pf = pos_h[t] * WW + pos_w[t];
    float4 x  = ((const float4*)patches)[i];
    float4 mn = *(const float4*)(g_mnew + (size_t)pf * P2 + p);
    float4 rs = *(const float4*)(g_rstd + (size_t)pf * P2 + p);
    float4 o;
    o.x = (x.x - mn.x) * rs.x;
    o.y = (x.y - mn.y) * rs.y;
    o.z = (x.z - mn.z) * rs.z;
    o.w = (x.w - mn.w) * rs.w;
    ((float4*)out)[i] = o;
}

// ---------------------------------------------------------------------------
extern "C" void kernel_launch(void* const* d_in, const int* in_sizes, int n_in,
                              void* d_out, int out_size) {
    const float* patches = (const float*)d_in[0];
    const int*   pos_h   = (const int*)d_in[1];
    const int*   pos_w   = (const int*)d_in[2];
    const int*   mask    = (const int*)d_in[3];    // bool widened to int32
    const float* n_in0   = (const float*)d_in[4];
    const float* mean_in = (const float*)d_in[5];
    const float* m2_in   = (const float*)d_in[6];
    float*       out     = (float*)d_out;

    k_zero <<<(HWB + 255) / 256, 256>>>();
    k_bin  <<<(NTOK + 255) / 256, 256>>>(pos_h, pos_w, mask);
    k_stats<<<HWB, P2>>>(patches, n_in0, mean_in, m2_in);
    k_norm <<<(NTOK * DD / 4 + 255) / 256, 256>>>(patches, pos_h, pos_w, mask, out);
}

// round 7
// speedup vs baseline: 1.3168x; 1.3168x over previous
#include <cuda_runtime.h>
#include <math.h>

#define BB 32
#define SS 1024
#define NTOK (BB*SS)      // 32768 tokens
#define HH 32
#define WW 32
#define HWB (HH*WW)       // 1024 bins
#define P2 256
#define CC 3
#define DD (CC*P2)        // 768
#define MAXB 192
#define EPSV 1e-6f

// ---- scratch (device globals; no allocation) ----
__device__ int   g_bincount[HWB];
__device__ int   g_binlist[HWB * MAXB];   // 768 KB
__device__ float g_mnew[HWB * P2];        // mean_new       (1 MB)
__device__ float g_rstd[HWB * P2];        // 1/(std+eps)    (1 MB)

// ---------------------------------------------------------------------------
// K0: zero bin counters (graph replays -> must reset every launch)
// ---------------------------------------------------------------------------
__global__ void k_zero() {
    int i = blockIdx.x * blockDim.x + threadIdx.x;
    if (i < HWB) g_bincount[i] = 0;
}

// ---------------------------------------------------------------------------
// K1: bin valid tokens by flat grid index pf (mask is int32; nonzero = pad)
// ---------------------------------------------------------------------------
__global__ void k_bin(const int* __restrict__ pos_h,
                      const int* __restrict__ pos_w,
                      const int* __restrict__ mask) {
    int t = blockIdx.x * blockDim.x + threadIdx.x;
    if (t >= NTOK) return;
    if (mask[t] != 0) return;
    int pf = pos_h[t] * WW + pos_w[t];
    int idx = atomicAdd(&g_bincount[pf], 1);
    if (idx < MAXB) g_binlist[pf * MAXB + idx] = t;
}

// ---------------------------------------------------------------------------
// K2: per-bin Welford update + rstd, one block per bin, thread = p column.
//     a_i = xbar_i - mean_old ; S1 = sum a ; S2 = sum a^2
//     mean_new = mo + S1/n_g ; m2_new = m2 + S2 - (S1/n_g)*S1
//     Unroll 4 over tokens -> 12 independent loads in flight.
// ---------------------------------------------------------------------------
__global__ void __launch_bounds__(P2) k_stats(const float* __restrict__ patches,
                                              const float* __restrict__ n_in,
                                              const float* __restrict__ mean_in,
                                              const float* __restrict__ m2_in) {
    int bin = blockIdx.x;
    int p = threadIdx.x;                         // 0..255

    __shared__ int s_tok[MAXB];
    __shared__ int s_cnt;
    if (p == 0) s_cnt = min(g_bincount[bin], MAXB);
    __syncthreads();
    int cnt = s_cnt;
    for (int i = p; i < cnt; i += P2) s_tok[i] = g_binlist[bin * MAXB + i];
    __syncthreads();

    float mo = mean_in[(size_t)bin * P2 + p];
    float s1 = 0.f, s2 = 0.f;
    const float c3 = 1.0f / 3.0f;

    int i = 0;
    for (; i + 4 <= cnt; i += 4) {
        const float* b0 = patches + (size_t)s_tok[i]     * DD;
        const float* b1 = patches + (size_t)s_tok[i + 1] * DD;
        const float* b2 = patches + (size_t)s_tok[i + 2] * DD;
        const float* b3 = patches + (size_t)s_tok[i + 3] * DD;
        float x00 = b0[p], x01 = b0[p + 256], x02 = b0[p + 512];
        float x10 = b1[p], x11 = b1[p + 256], x12 = b1[p + 512];
        float x20 = b2[p], x21 = b2[p + 256], x22 = b2[p + 512];
        float x30 = b3[p], x31 = b3[p + 256], x32 = b3[p + 512];
        float a0 = (x00 + x01 + x02) * c3 - mo;
        float a1 = (x10 + x11 + x12) * c3 - mo;
        float a2 = (x20 + x21 + x22) * c3 - mo;
        float a3 = (x30 + x31 + x32) * c3 - mo;
        s1 += a0; s2 += a0 * a0;
        s1 += a1; s2 += a1 * a1;
        s1 += a2; s2 += a2 * a2;
        s1 += a3; s2 += a3 * a3;
    }
    for (; i < cnt; i++) {
        const float* b0 = patches + (size_t)s_tok[i] * DD;
        float a0 = (b0[p] + b0[p + 256] + b0[p + 512]) * c3 - mo;
        s1 += a0; s2 += a0 * a0;
    }

    float nn  = n_in[bin] + (float)cnt;
    float ng  = fmaxf(nn, 1.0f);
    float u   = s1 / ng;
    float mnv = mo + u;
    float m2v = m2_in[(size_t)bin * P2 + p] + (s2 - u * s1);
    float var = (nn < 2.0f) ? 1.0f : (m2v / ng);

    g_mnew[(size_t)bin * P2 + p] = mnv;
    g_rstd[(size_t)bin * P2 + p] = 1.0f / (sqrtf(var) + EPSV);
}

// ---------------------------------------------------------------------------
// K3: normalize. 64 lanes per token; lane l owns stat column p = 4l and
//     processes all 3 channels -> stats gathered once, 5 loads in flight.
//     Block = 256 threads = 4 tokens.
// ---------------------------------------------------------------------------
__global__ void __launch_bounds__(256) k_norm(const float* __restrict__ patches,
                                              const int* __restrict__ pos_h,
                                              const int* __restrict__ pos_w,
                                              const int* __restrict__ mask,
                                              float* __restrict__ out) {
    int t = blockIdx.x * 4 + (threadIdx.x >> 6);
    int lane = threadIdx.x & 63;
    if (t >= NTOK) return;

    const float4* xr = (const float4*)(patches + (size_t)t * DD);
    float4*       orow = (float4*)(out + (size_t)t * DD);

    if (mask[t] != 0) {
        float4 z = make_float4(0.f, 0.f, 0.f, 0.f);
        orow[lane] = z; orow[lane + 64] = z; orow[lane + 128] = z;
        return;
    }
    int pf = pos_h[t] * WW + pos_w[t];

    // issue all 5 loads before any consumer
    float4 x0 = xr[lane];
    float4 x1 = xr[lane + 64];
    float4 x2 = xr[lane + 128];
    float4 mn = ((const float4*)(g_mnew + (size_t)pf * P2))[lane];
    float4 rs = ((const float4*)(g_rstd + (size_t)pf * P2))[lane];

    float4 o0, o1, o2;
    o0.x = (x0.x - mn.x) * rs.x; o0.y = (x0.y - mn.y) * rs.y;
    o0.z = (x0.z - mn.z) * rs.z; o0.w = (x0.w - mn.w) * rs.w;
    o1.x = (x1.x - mn.x) * rs.x; o1.y = (x1.y - mn.y) * rs.y;
    o1.z = (x1.z - mn.z) * rs.z; o1.w = (x1.w - mn.w) * rs.w;
    o2.x = (x2.x - mn.x) * rs.x; o2.y = (x2.y - mn.y) * rs.y;
    o2.z = (x2.z - mn.z) * rs.z; o2.w = (x2.w - mn.w) * rs.w;

    orow[lane]       = o0;
    orow[lane + 64]  = o1;
    orow[lane + 128] = o2;
}

// ---------------------------------------------------------------------------
extern "C" void kernel_launch(void* const* d_in, const int* in_sizes, int n_in,
                              void* d_out, int out_size) {
    const float* patches = (const float*)d_in[0];
    const int*   pos_h   = (const int*)d_in[1];
    const int*   pos_w   = (const int*)d_in[2];
    const int*   mask    = (const int*)d_in[3];    // bool widened to int32
    const float* n_in0   = (const float*)d_in[4];
    const float* mean_in = (const float*)d_in[5];
    const float* m2_in   = (const float*)d_in[6];
    float*       out     = (float*)d_out;

    k_zero <<<(HWB + 255) / 256, 256>>>();
    k_bin  <<<(NTOK + 255) / 256, 256>>>(pos_h, pos_w, mask);
    k_stats<<<HWB, P2>>>(patches, n_in0, mean_in, m2_in);
    k_norm <<<NTOK / 4, 256>>>(patches, pos_h, pos_w, mask, out);
}